// round 13
// baseline (speedup 1.0000x reference)
#include <cuda_runtime.h>

// Problem constants
static constexpr int Tt = 4;
static constexpr int Bb = 16;
static constexpr int Cc = 512;
static constexpr int Nn = 1024;
static constexpr int Cr = 64;
static constexpr int TB = Tt * Bb;     // 64 rows
static constexpr int BC = Bb * Cc;     // 8192 channels
static constexpr int NBLK = BC / 2;    // 4096 phase-A blocks (2 channels each)

// Scratch (allocation-free: __device__ globals)
__device__ float g_buf[TB * Cc];       // GAP output [64, 512] row-major [r][c]
__device__ float h1nT_buf[Cr * TB];    // bn1 output TRANSPOSED [j][r]
// Monotonic counters (never reset; each launch adds exactly NBLK / 64, so the
// ceil-division barrier id is launch-count independent — proven R3..R12).
__device__ unsigned g_done;            // phase-A completions (NBLK per launch)
__device__ unsigned g_tb;              // tail-block arrivals (64 per launch)

// Scaled-LIF step (exact, bit-identical; verified rel_err=0 in R9/R10/R12):
// u_t = v_t * 2^t; u += x*2^t; spike iff u >= 2^(t+1); hard reset u = 0.
#define ULIF(u, xv, CT, TH, pk, INC) \
    do { u = fmaf((xv), (CT), u); if (u >= (TH)) { pk += (INC); u = 0.0f; } } while (0)

__global__ void __launch_bounds__(256)
snn_kernel(const float* __restrict__ x,
           const float* __restrict__ w1, const float* __restrict__ b1,
           const float* __restrict__ gamma1, const float* __restrict__ beta1,
           const float* __restrict__ w2, const float* __restrict__ b2,
           const float* __restrict__ gamma2, const float* __restrict__ beta2,
           float* __restrict__ out)
{
    const int tid  = threadIdx.x;
    const int lane = tid & 31;
    const int warp = tid >> 5;

    __shared__ unsigned sdata[8][2];        // phase A packed counts [warp][ch]
    __shared__ unsigned sv;                 // broadcast of done-counter value
    __shared__ float ws[Cc];                // phase B: w1 row
    __shared__ float h1s[TB];               // phase B: column values
    __shared__ float stats[2];              // phase B: mu, scale
    __shared__ float hT[Cr * (TB + 1)];     // phase C: h1nT padded [j*65+r]
    __shared__ float w2s[8 * Cr];           // phase C: 8 w2 rows
    __shared__ float wsum[32];              // phase C: warp partials

    // =====================================================================
    // Phase A: LIF multistep + GAP. ONE task per block (flat, R2/R8-proven
    // shape): 2 channels, 8 front-batched LDG.128 per thread, no loop.
    // =====================================================================
    {
        const int bc0 = blockIdx.x * 2;
        const int bc1 = bc0 + 1;
        const float4* __restrict__ xp = reinterpret_cast<const float4*>(x);

        float4 xa[Tt], xb[Tt];
        #pragma unroll
        for (int t = 0; t < Tt; t++) {
            xa[t] = xp[(size_t)(t * BC + bc0) * 256 + tid];
            xb[t] = xp[(size_t)(t * BC + bc1) * 256 + tid];
        }

        float ua0=0.f, ua1=0.f, ua2=0.f, ua3=0.f;
        float ub0=0.f, ub1=0.f, ub2=0.f, ub3=0.f;
        unsigned pa = 0u, pb = 0u;

        #pragma unroll
        for (int t = 0; t < Tt; t++) {
            const float    CT  = (float)(1 << t);   // 2^t
            const float    TH  = (float)(2 << t);   // 2^(t+1)
            const unsigned INC = 1u << (8 * t);
            ULIF(ua0, xa[t].x, CT, TH, pa, INC);
            ULIF(ua1, xa[t].y, CT, TH, pa, INC);
            ULIF(ua2, xa[t].z, CT, TH, pa, INC);
            ULIF(ua3, xa[t].w, CT, TH, pa, INC);
            ULIF(ub0, xb[t].x, CT, TH, pb, INC);
            ULIF(ub1, xb[t].y, CT, TH, pb, INC);
            ULIF(ub2, xb[t].z, CT, TH, pb, INC);
            ULIF(ub3, xb[t].w, CT, TH, pb, INC);
        }

        pa = __reduce_add_sync(0xffffffffu, pa);
        pb = __reduce_add_sync(0xffffffffu, pb);
        if (lane == 0) { sdata[warp][0] = pa; sdata[warp][1] = pb; }
        __syncthreads();

        if (tid < 8) {
            const int ch = tid >> 2;
            const int t  = tid & 3;
            unsigned s = 0;
            #pragma unroll
            for (int w = 0; w < 8; w++)
                s += (sdata[w][ch] >> (8 * t)) & 0xFFu;
            g_buf[t * BC + bc0 + ch] = (float)s * (1.0f / (float)Nn);
        }
    }

    // ---- completion counting; last 64 blocks become the tail ----
    __syncthreads();
    if (tid == 0) {
        __threadfence();                         // publish g_buf writes
        sv = atomicAdd(&g_done, 1u) + 1u;
    }
    __syncthreads();
    const unsigned v = sv;
    const unsigned B = (v + (unsigned)NBLK - 1u) / (unsigned)NBLK;  // launch id
    const int j = (int)(B * (unsigned)NBLK - v);  // 0..NBLK-1, 0 = very last
    if (j >= Cr) return;                           // not a tail block

    // Wait until ALL phase-A blocks of this launch are done (tail blocks are
    // resident by construction; non-tail blocks retire independently).
    if (tid == 0) {
        while (*(volatile unsigned*)&g_done < B * (unsigned)NBLK) __nanosleep(64);
        __threadfence();
    }
    __syncthreads();

    // =====================================================================
    // Phase B: mm1 + bn1 for output column j (R9/R12-proven body).
    // =====================================================================
    {
        for (int i = tid; i < Cc; i += 256) ws[i] = w1[(size_t)j * Cc + i];
        __syncthreads();

        float acc[8];
        #pragma unroll
        for (int k = 0; k < 8; k++) acc[k] = 0.f;

        #pragma unroll
        for (int i = 0; i < 16; i++) {
            const int col = i * 32 + lane;
            const float wv = ws[col];
            #pragma unroll
            for (int k = 0; k < 8; k++)
                acc[k] += g_buf[(size_t)(warp * 8 + k) * Cc + col] * wv;
        }

        const float b1j = b1[j];
        #pragma unroll
        for (int k = 0; k < 8; k++) {
            float val = acc[k];
            #pragma unroll
            for (int off = 16; off > 0; off >>= 1)
                val += __shfl_down_sync(0xffffffffu, val, off);
            if (lane == 0) h1s[warp * 8 + k] = val + b1j;
        }
        __syncthreads();

        if (warp == 0) {
            float a = h1s[lane], b = h1s[lane + 32];
            float s  = a + b;
            float ss = a * a + b * b;
            #pragma unroll
            for (int off = 16; off > 0; off >>= 1) {
                s  += __shfl_down_sync(0xffffffffu, s,  off);
                ss += __shfl_down_sync(0xffffffffu, ss, off);
            }
            if (lane == 0) {
                float mu  = s * (1.0f / TB);
                float var = ss * (1.0f / TB) - mu * mu;
                if (var < 0.f) var = 0.f;
                stats[0] = mu;
                stats[1] = rsqrtf(var + 1e-5f) * gamma1[j];
            }
        }
        __syncthreads();

        if (tid < TB)
            h1nT_buf[j * TB + tid] = (h1s[tid] - stats[0]) * stats[1] + beta1[j];
    }

    // ---- mini grid barrier among the 64 (all-resident) tail blocks ----
    {
        __threadfence();
        __syncthreads();
        if (tid == 0) {
            unsigned v2 = atomicAdd(&g_tb, 1u) + 1u;
            unsigned B2 = (v2 + 63u) / 64u;
            while (*(volatile unsigned*)&g_tb < B2 * 64u) __nanosleep(32);
            __threadfence();
        }
        __syncthreads();
    }

    // =====================================================================
    // Phase C: mm2 + bn2 + out; this block owns 8 consecutive columns.
    // 4 column-groups of 64 threads, 2 passes (R7-debugged structure).
    // =====================================================================
    {
        const int c0 = j * 8;

        // Stage h1nT (coalesced float4) into padded smem.
        {
            const float4* __restrict__ hp = reinterpret_cast<const float4*>(h1nT_buf);
            #pragma unroll
            for (int u = 0; u < 4; u++) {
                const int i4 = u * 256 + tid;
                float4 val = hp[i4];
                const int i  = i4 * 4;
                const int jj = i >> 6, rr = i & 63;
                float* d = &hT[jj * 65 + rr];
                d[0] = val.x; d[1] = val.y; d[2] = val.z; d[3] = val.w;
            }
        }
        // Stage 8 consecutive w2 rows = 512 consecutive floats.
        for (int i = tid; i < 8 * Cr; i += 256)
            w2s[i] = w2[(size_t)c0 * Cr + i];
        __syncthreads();

        const int q  = tid >> 6;        // column group 0..3
        const int r  = tid & 63;        // row 0..63
        const int gw = (tid >> 5) & 1;  // warp within group

        #pragma unroll
        for (int p = 0; p < 2; p++) {
            const int k = p * 4 + q;
            const int c = c0 + k;

            float acc = 0.f;
            const float* __restrict__ wr = w2s + k * Cr;
            #pragma unroll
            for (int jj = 0; jj < Cr; jj++)
                acc += hT[jj * 65 + r] * wr[jj];
            const float h = acc + b2[c];

            float s = h, ss = h * h;
            #pragma unroll
            for (int off = 16; off > 0; off >>= 1) {
                s  += __shfl_down_sync(0xffffffffu, s,  off);
                ss += __shfl_down_sync(0xffffffffu, ss, off);
            }
            float* wp = wsum + (p * 16 + q * 4 + gw * 2);
            if (lane == 0) { wp[0] = s; wp[1] = ss; }
            __syncthreads();

            const float* w0 = wsum + (p * 16 + q * 4);
            const float S  = w0[0] + w0[2];
            const float SS = w0[1] + w0[3];
            const float mu = S * (1.0f / TB);
            float var = SS * (1.0f / TB) - mu * mu;
            if (var < 0.f) var = 0.f;
            const float sc = rsqrtf(var + 1e-5f) * gamma2[c];
            out[r * Cc + c] = (h - mu) * sc + beta2[c];
        }
    }
}

// ---------------------------------------------------------------------------
extern "C" void kernel_launch(void* const* d_in, const int* in_sizes, int n_in,
                              void* d_out, int out_size) {
    const float* x      = (const float*)d_in[0];
    const float* w1     = (const float*)d_in[1];
    const float* b1     = (const float*)d_in[2];
    const float* gamma1 = (const float*)d_in[3];
    const float* beta1  = (const float*)d_in[4];
    const float* w2     = (const float*)d_in[5];
    const float* b2     = (const float*)d_in[6];
    const float* gamma2 = (const float*)d_in[7];
    const float* beta2  = (const float*)d_in[8];
    float* out = (float*)d_out;

    snn_kernel<<<NBLK, 256>>>(x, w1, b1, gamma1, beta1,
                              w2, b2, gamma2, beta2, out);
}

// round 14
// speedup vs baseline: 1.1665x; 1.1665x over previous
#include <cuda_runtime.h>

// Problem constants
static constexpr int Tt = 4;
static constexpr int Bb = 16;
static constexpr int Cc = 512;
static constexpr int Nn = 1024;
static constexpr int Cr = 64;
static constexpr int TB = Tt * Bb;     // 64 rows
static constexpr int BC = Bb * Cc;     // 8192 channels (= phase-A tasks)
static constexpr int MAX_SLOTS = 32;   // supports nb >= 256 resident blocks

// Scratch (allocation-free: __device__ globals)
__device__ float g_buf[TB * Cc];       // GAP output [64, 512] row-major [r][c]
__device__ float h1nT_buf[Cr * TB];    // bn1 output TRANSPOSED [j][r]
// Monotonic grid-barrier state (2 syncs per launch, nb arrivals each ->
// counter is a multiple of nb at every launch start; barrier id
// B = ceil(v/nb) is launch-count independent). Proven R3..R12.
__device__ unsigned g_arrive;
__device__ volatile unsigned g_release;

// Scaled-LIF step (exact, bit-identical; verified rel_err=0 R9/R10/R12):
// u_t = v_t * 2^t; u += x*2^t; spike iff u >= 2^(t+1); hard reset u = 0.
#define ULIF(u, xv, CT, TH, pk, INC) \
    do { u = fmaf((xv), (CT), u); if (u >= (TH)) { pk += (INC); u = 0.0f; } } while (0)

// Full 16-step LIF for one channel's float4-quad -> packed byte counters.
#define LIF_TASK(Q0, Q1, Q2, Q3, p)                       \
    do {                                                  \
        float u0 = 0.f, u1 = 0.f, u2 = 0.f, u3 = 0.f;     \
        ULIF(u0, Q0.x, 1.f, 2.f, p, 1u);                  \
        ULIF(u1, Q0.y, 1.f, 2.f, p, 1u);                  \
        ULIF(u2, Q0.z, 1.f, 2.f, p, 1u);                  \
        ULIF(u3, Q0.w, 1.f, 2.f, p, 1u);                  \
        ULIF(u0, Q1.x, 2.f, 4.f, p, 1u << 8);             \
        ULIF(u1, Q1.y, 2.f, 4.f, p, 1u << 8);             \
        ULIF(u2, Q1.z, 2.f, 4.f, p, 1u << 8);             \
        ULIF(u3, Q1.w, 2.f, 4.f, p, 1u << 8);             \
        ULIF(u0, Q2.x, 4.f, 8.f, p, 1u << 16);            \
        ULIF(u1, Q2.y, 4.f, 8.f, p, 1u << 16);            \
        ULIF(u2, Q2.z, 4.f, 8.f, p, 1u << 16);            \
        ULIF(u3, Q2.w, 4.f, 8.f, p, 1u << 16);            \
        ULIF(u0, Q3.x, 8.f, 16.f, p, 1u << 24);           \
        ULIF(u1, Q3.y, 8.f, 16.f, p, 1u << 24);           \
        ULIF(u2, Q3.z, 8.f, 16.f, p, 1u << 24);           \
        ULIF(u3, Q3.w, 8.f, 16.f, p, 1u << 24);           \
    } while (0)

__global__ void __launch_bounds__(256, 4)
fused_kernel(const float* __restrict__ x,
             const float* __restrict__ w1, const float* __restrict__ b1,
             const float* __restrict__ gamma1, const float* __restrict__ beta1,
             const float* __restrict__ w2, const float* __restrict__ b2,
             const float* __restrict__ gamma2, const float* __restrict__ beta2,
             float* __restrict__ out, int nb)
{
    const int tid  = threadIdx.x;
    const int lane = tid & 31;
    const int warp = tid >> 5;

    __shared__ unsigned sdataA[MAX_SLOTS][8];  // phase A: per-slot packed counts
    __shared__ float ws[Cc];                   // phase B: w1 row
    __shared__ float h1s[TB];                  // phase B: column values
    __shared__ float stats[2];                 // phase B: mu, scale
    __shared__ float hT[Cr * (TB + 1)];        // phase C: h1nT padded [j*65+r]
    __shared__ float w2s[Cr];                  // phase C: w2 row
    __shared__ float wsum[4];                  // phase C: warp partials

    auto grid_sync = [&]() {
        __threadfence();
        __syncthreads();
        if (tid == 0) {
            unsigned v = atomicAdd(&g_arrive, 1u) + 1u;
            unsigned B = (v + (unsigned)nb - 1u) / (unsigned)nb;
            if (v == B * (unsigned)nb) g_release = B;
            while (g_release < B) { __nanosleep(32); }
            __threadfence();
        }
        __syncthreads();
    };

    // =====================================================================
    // Phase A: LIF multistep + GAP. One channel per task, 2-DEEP register
    // pipeline: while computing task i, the loads of tasks i+1 AND i+2 are
    // in flight. One REDUX per task; slots flushed after a single barrier.
    // =====================================================================
    {
        const float4* __restrict__ xp = reinterpret_cast<const float4*>(x);
        int nslots = 0;

        int tC = blockIdx.x;          // current task
        int tP = tC + 2 * nb;         // task to prefetch each iteration

        float4 A0, A1, A2, A3, B0, B1, B2, B3;
        if (tC < BC) {
            A0 = xp[(size_t)(0 * BC + tC) * 256 + tid];
            A1 = xp[(size_t)(1 * BC + tC) * 256 + tid];
            A2 = xp[(size_t)(2 * BC + tC) * 256 + tid];
            A3 = xp[(size_t)(3 * BC + tC) * 256 + tid];
        }
        if (tC + nb < BC) {
            const int t1 = tC + nb;
            B0 = xp[(size_t)(0 * BC + t1) * 256 + tid];
            B1 = xp[(size_t)(1 * BC + t1) * 256 + tid];
            B2 = xp[(size_t)(2 * BC + t1) * 256 + tid];
            B3 = xp[(size_t)(3 * BC + t1) * 256 + tid];
        }

        while (tC < BC) {
            float4 C0, C1, C2, C3;
            if (tP < BC) {
                C0 = xp[(size_t)(0 * BC + tP) * 256 + tid];
                C1 = xp[(size_t)(1 * BC + tP) * 256 + tid];
                C2 = xp[(size_t)(2 * BC + tP) * 256 + tid];
                C3 = xp[(size_t)(3 * BC + tP) * 256 + tid];
            }

            unsigned p = 0u;
            LIF_TASK(A0, A1, A2, A3, p);
            p = __reduce_add_sync(0xffffffffu, p);
            if (lane == 0) sdataA[nslots][warp] = p;
            nslots++;

            // rotate pipeline
            A0 = B0; A1 = B1; A2 = B2; A3 = B3;
            B0 = C0; B1 = C1; B2 = C2; B3 = C3;
            tC += nb;
            tP += nb;
        }

        __syncthreads();   // the ONLY phase-A block barrier

        for (int sl = 0; sl < nslots; sl++) {
            if (tid < 4) {
                unsigned s = 0;
                #pragma unroll
                for (int w = 0; w < 8; w++)
                    s += (sdataA[sl][w] >> (8 * tid)) & 0xFFu;
                const int tk = blockIdx.x + sl * nb;
                g_buf[tid * BC + tk] = (float)s * (1.0f / (float)Nn);
            }
        }
    }

    grid_sync();

    // =====================================================================
    // Phase B: mm1 + bn1. Blocks 0..63 own output column j (R12 body).
    // =====================================================================
    if (blockIdx.x < Cr) {
        const int j = blockIdx.x;

        for (int i = tid; i < Cc; i += 256) ws[i] = w1[(size_t)j * Cc + i];
        __syncthreads();

        float acc[8];
        #pragma unroll
        for (int k = 0; k < 8; k++) acc[k] = 0.f;

        #pragma unroll
        for (int i = 0; i < 16; i++) {
            const int col = i * 32 + lane;
            const float wv = ws[col];
            #pragma unroll
            for (int k = 0; k < 8; k++)
                acc[k] += g_buf[(size_t)(warp * 8 + k) * Cc + col] * wv;
        }

        const float b1j = b1[j];
        #pragma unroll
        for (int k = 0; k < 8; k++) {
            float v = acc[k];
            #pragma unroll
            for (int off = 16; off > 0; off >>= 1)
                v += __shfl_down_sync(0xffffffffu, v, off);
            if (lane == 0) h1s[warp * 8 + k] = v + b1j;
        }
        __syncthreads();

        if (warp == 0) {
            float a = h1s[lane], b = h1s[lane + 32];
            float s  = a + b;
            float ss = a * a + b * b;
            #pragma unroll
            for (int off = 16; off > 0; off >>= 1) {
                s  += __shfl_down_sync(0xffffffffu, s,  off);
                ss += __shfl_down_sync(0xffffffffu, ss, off);
            }
            if (lane == 0) {
                float mu  = s * (1.0f / TB);
                float var = ss * (1.0f / TB) - mu * mu;
                if (var < 0.f) var = 0.f;
                stats[0] = mu;
                stats[1] = rsqrtf(var + 1e-5f) * gamma1[j];
            }
        }
        __syncthreads();

        if (tid < TB)
            h1nT_buf[j * TB + tid] = (h1s[tid] - stats[0]) * stats[1] + beta1[j];
    }

    grid_sync();

    // =====================================================================
    // Phase C: mm2 + bn2 + out. Block c owns output column c (R12 body).
    // =====================================================================
    if (blockIdx.x < Cc) {
        {
            const float4* __restrict__ hp = reinterpret_cast<const float4*>(h1nT_buf);
            #pragma unroll
            for (int u = 0; u < 4; u++) {
                const int i4 = u * 256 + tid;
                float4 v = hp[i4];
                const int i  = i4 * 4;
                const int jj = i >> 6, rr = i & 63;
                float* d = &hT[jj * 65 + rr];
                d[0] = v.x; d[1] = v.y; d[2] = v.z; d[3] = v.w;
            }
        }

        for (int c = blockIdx.x; c < Cc; c += nb) {
            if (tid < Cr) w2s[tid] = w2[(size_t)c * Cr + tid];
            __syncthreads();

            float h = 0.f;
            if (tid < TB) {
                float acc = 0.f;
                #pragma unroll
                for (int j = 0; j < Cr; j++)
                    acc += hT[j * 65 + tid] * w2s[j];
                h = acc + b2[c];

                float s = h, ss = h * h;
                #pragma unroll
                for (int off = 16; off > 0; off >>= 1) {
                    s  += __shfl_down_sync(0xffffffffu, s,  off);
                    ss += __shfl_down_sync(0xffffffffu, ss, off);
                }
                if (lane == 0) { wsum[warp * 2] = s; wsum[warp * 2 + 1] = ss; }
            }
            __syncthreads();

            if (tid < TB) {
                const float S  = wsum[0] + wsum[2];
                const float SS = wsum[1] + wsum[3];
                const float mu = S * (1.0f / TB);
                float var = SS * (1.0f / TB) - mu * mu;
                if (var < 0.f) var = 0.f;
                const float sc = rsqrtf(var + 1e-5f) * gamma2[c];
                out[tid * Cc + c] = (h - mu) * sc + beta2[c];
            }
            __syncthreads();
        }
    }
}

// ---------------------------------------------------------------------------
extern "C" void kernel_launch(void* const* d_in, const int* in_sizes, int n_in,
                              void* d_out, int out_size) {
    const float* x      = (const float*)d_in[0];
    const float* w1     = (const float*)d_in[1];
    const float* b1     = (const float*)d_in[2];
    const float* gamma1 = (const float*)d_in[3];
    const float* beta1  = (const float*)d_in[4];
    const float* w2     = (const float*)d_in[5];
    const float* b2     = (const float*)d_in[6];
    const float* gamma2 = (const float*)d_in[7];
    const float* beta2  = (const float*)d_in[8];
    float* out = (float*)d_out;

    int dev = 0, sms = 0, maxb = 0;
    cudaGetDevice(&dev);
    cudaDeviceGetAttribute(&sms, cudaDevAttrMultiProcessorCount, dev);
    cudaOccupancyMaxActiveBlocksPerMultiprocessor(&maxb, fused_kernel, 256, 0);
    if (sms < 1) sms = 1;
    if (maxb < 1) maxb = 1;
    int nb = sms * maxb;              // all resident (required for grid sync)
    if (nb > BC) nb = BC;             // MAX_SLOTS=32 covers nb >= 256

    fused_kernel<<<nb, 256>>>(x, w1, b1, gamma1, beta1,
                              w2, b2, gamma2, beta2, out, nb);
}